// round 8
// baseline (speedup 1.0000x reference)
#include <cuda_runtime.h>
#include <cuda_bf16.h>
#include <cstdint>

// Problem constants (fixed by the dataset)
#define DHEAD 128
#define MPROJ 128
#define NQ    4096
#define NK    8192
#define SCALE_CONST 0.009791516698f  // sqrt(pi/2)/128

// ---------------- device-global scratch (pre-swizzled SW128 slab layout) -------
// g_qhi/g_qlo: 128-row tiles of 32KB; within tile: two 16KB slabs (64 K-cols),
//              slab offset = swizzle128(row*128 + col*2).
// g_signs:     256-row tiles of 64KB; within tile: two 32KB slabs.
__device__ __nv_bfloat16 g_signs[NK * MPROJ];
__device__ float         g_nscale[NK];
__device__ __nv_bfloat16 g_qhi[NQ * MPROJ];
__device__ __nv_bfloat16 g_qlo[NQ * MPROJ];

__device__ __forceinline__ uint32_t sw128(uint32_t x) { return x ^ ((x >> 3) & 0x70); }

// ================================================================================
// Prep: fp32 GEMM rows @ S^T. 32 rows/block.
//   blocks [0,256): residual -> signs (bf16 ±1, swizzled) + nscale
//   blocks [256,384): query  -> q_proj hi/lo (bf16, swizzled)
// ================================================================================
#define PREP_ROWS 32
#define PREP_THREADS 256
#define PADP 129
#define PREP_SMEM_BYTES ((PREP_ROWS * PADP + MPROJ * PADP) * 4)

__global__ __launch_bounds__(PREP_THREADS)
void qjl_prep_kernel(const float* __restrict__ query,
                     const float* __restrict__ residual,
                     const float* __restrict__ S)
{
    extern __shared__ float smf[];
    float* Ash = smf;                       // [32][129]
    float* Ssh = smf + PREP_ROWS * PADP;    // [128][129]

    const int tid = threadIdx.x;
    const bool is_res = (blockIdx.x < (NK / PREP_ROWS));
    const int rbase = is_res ? blockIdx.x * PREP_ROWS
                             : (blockIdx.x - NK / PREP_ROWS) * PREP_ROWS;
    const float* src = is_res ? residual : query;

    const float4* gA = (const float4*)(src + (size_t)rbase * DHEAD);
    #pragma unroll
    for (int idx = tid; idx < PREP_ROWS * 32; idx += PREP_THREADS) {
        int r = idx >> 5, c4 = idx & 31;
        float4 v = gA[idx];
        float* d = Ash + r * PADP + c4 * 4;
        d[0] = v.x; d[1] = v.y; d[2] = v.z; d[3] = v.w;
    }
    const float4* gS = (const float4*)S;
    #pragma unroll
    for (int idx = tid; idx < MPROJ * 32; idx += PREP_THREADS) {
        int r = idx >> 5, c4 = idx & 31;
        float4 v = gS[idx];
        float* d = Ssh + r * PADP + c4 * 4;
        d[0] = v.x; d[1] = v.y; d[2] = v.z; d[3] = v.w;
    }
    __syncthreads();

    if (is_res && tid < PREP_ROWS) {
        float s = 0.f;
        #pragma unroll 8
        for (int k = 0; k < DHEAD; k++) {
            float a = Ash[tid * PADP + k];
            s += a * a;
        }
        g_nscale[rbase + tid] = sqrtf(s) * SCALE_CONST;
    }

    const int rg = tid & 15;   // 2 rows per thread
    const int cg = tid >> 4;   // 8 cols per thread

    float acc[2][8];
    #pragma unroll
    for (int i = 0; i < 2; i++)
        #pragma unroll
        for (int j = 0; j < 8; j++) acc[i][j] = 0.f;

    #pragma unroll 4
    for (int k = 0; k < DHEAD; k++) {
        float a[2], b[8];
        #pragma unroll
        for (int i = 0; i < 2; i++) a[i] = Ash[(2 * rg + i) * PADP + k];
        #pragma unroll
        for (int j = 0; j < 8; j++) b[j] = Ssh[(8 * cg + j) * PADP + k];
        #pragma unroll
        for (int i = 0; i < 2; i++)
            #pragma unroll
            for (int j = 0; j < 8; j++)
                acc[i][j] = fmaf(a[i], b[j], acc[i][j]);
    }

    const int col8 = 8 * cg;              // col base (0..120)
    if (is_res) {
        #pragma unroll
        for (int i = 0; i < 2; i++) {
            union { __nv_bfloat16 h[8]; uint4 u; } pk;
            #pragma unroll
            for (int j = 0; j < 8; j++)
                pk.h[j] = __float2bfloat16(acc[i][j] >= 0.f ? 1.f : -1.f);
            int row = rbase + 2 * rg + i;
            uint32_t off = (uint32_t)(row >> 8) * 65536u
                         + (uint32_t)(col8 >> 6) * 32768u
                         + sw128((uint32_t)(row & 255) * 128u + (uint32_t)(col8 & 63) * 2u);
            *(uint4*)((char*)g_signs + off) = pk.u;
        }
    } else {
        #pragma unroll
        for (int i = 0; i < 2; i++) {
            union { __nv_bfloat16 h[8]; uint4 u; } ph, pl;
            #pragma unroll
            for (int j = 0; j < 8; j++) {
                float x = acc[i][j];
                __nv_bfloat16 hb = __float2bfloat16(x);
                ph.h[j] = hb;
                pl.h[j] = __float2bfloat16(x - __bfloat162float(hb));
            }
            int row = rbase + 2 * rg + i;
            uint32_t off = (uint32_t)(row >> 7) * 32768u
                         + (uint32_t)(col8 >> 6) * 16384u
                         + sw128((uint32_t)(row & 127) * 128u + (uint32_t)(col8 & 63) * 2u);
            *(uint4*)((char*)g_qhi + off) = ph.u;
            *(uint4*)((char*)g_qlo + off) = pl.u;
        }
    }
}

// ================================================================================
// Main GEMM via mma.sync bf16 (hi+lo). CTA tile 128q x 256k, K=128.
// 8 warps, warp tile 64x64. Swizzled SW128 smem, linear fill (prep pre-swizzles).
// ================================================================================
#define MT3 256
#define SM_NSC 0                    // 256 floats = 1024 B
#define SM_AH  1024                 // 32 KB (two 16KB slabs of 64 K-cols)
#define SM_AL  (SM_AH + 32768)      // 32 KB
#define SM_B   (SM_AL + 32768)      // 64 KB (two 32KB slabs)
#define MAIN_SMEM_BYTES (SM_B + 65536)

__device__ __forceinline__ void ldm_x4(uint32_t* r, uint32_t addr) {
    asm volatile("ldmatrix.sync.aligned.m8n8.x4.shared.b16 {%0,%1,%2,%3}, [%4];"
                 : "=r"(r[0]), "=r"(r[1]), "=r"(r[2]), "=r"(r[3])
                 : "r"(addr));
}

__device__ __forceinline__ void mma_bf16(float* d, const uint32_t* a,
                                         uint32_t b0, uint32_t b1) {
    asm volatile(
        "mma.sync.aligned.m16n8k16.row.col.f32.bf16.bf16.f32 "
        "{%0,%1,%2,%3}, {%4,%5,%6,%7}, {%8,%9}, {%0,%1,%2,%3};"
        : "+f"(d[0]), "+f"(d[1]), "+f"(d[2]), "+f"(d[3])
        : "r"(a[0]), "r"(a[1]), "r"(a[2]), "r"(a[3]), "r"(b0), "r"(b1));
}

__global__ __launch_bounds__(MT3, 1)
void qjl_mma_kernel(float* __restrict__ out)
{
    extern __shared__ char smem[];
    uint32_t sb;
    asm("{ .reg .u64 t; cvta.to.shared.u64 t, %1; cvt.u32.u64 %0, t; }"
        : "=r"(sb) : "l"(smem));

    const int tid = threadIdx.x;
    const int warp = tid >> 5, lane = tid & 31;
    const int qtile = blockIdx.y * 128;
    const int ktile = blockIdx.x * 256;

    // ---- linear fills (global layout is pre-swizzled) ----
    const uint4* gAh = (const uint4*)((const char*)g_qhi   + (size_t)(qtile >> 7) * 32768);
    const uint4* gAl = (const uint4*)((const char*)g_qlo   + (size_t)(qtile >> 7) * 32768);
    const uint4* gB  = (const uint4*)((const char*)g_signs + (size_t)(ktile >> 8) * 65536);
    uint4* sAh = (uint4*)(smem + SM_AH);
    uint4* sAl = (uint4*)(smem + SM_AL);
    uint4* sB  = (uint4*)(smem + SM_B);
    #pragma unroll
    for (int i = tid; i < 2048; i += MT3) {
        sAh[i] = gAh[i];
        sAl[i] = gAl[i];
    }
    #pragma unroll
    for (int i = tid; i < 4096; i += MT3) sB[i] = gB[i];
    float* nscs = (float*)(smem + SM_NSC);
    nscs[tid] = g_nscale[ktile + tid];
    __syncthreads();

    const int wm = warp >> 2;          // 0..1  (M half)
    const int wn = warp & 3;           // 0..3  (N quarter)
    const int lr = lane & 15;          // ldmatrix row within 16
    const int lcB = (lane >> 4) * 16;  // byte offset of 8-col group

    float acc[4][8][4];
    #pragma unroll
    for (int i = 0; i < 4; i++)
        #pragma unroll
        for (int j = 0; j < 8; j++)
            #pragma unroll
            for (int t = 0; t < 4; t++) acc[i][j][t] = 0.f;

    #pragma unroll
    for (int ks = 0; ks < 8; ks++) {
        const uint32_t kb = (uint32_t)(ks & 3) * 32u + lcB;   // byte col in slab
        const uint32_t aslab = sb + SM_AH + (ks >> 2) * 16384;
        const uint32_t lslab = sb + SM_AL + (ks >> 2) * 16384;
        const uint32_t bslab = sb + SM_B  + (ks >> 2) * 32768;

        uint32_t ah[4][4], al[4][4], bb[4][4];
        #pragma unroll
        for (int i = 0; i < 4; i++) {
            uint32_t row = wm * 64 + i * 16 + lr;
            uint32_t so = sw128(row * 128u + kb);
            ldm_x4(ah[i], aslab + so);
            ldm_x4(al[i], lslab + so);
        }
        #pragma unroll
        for (int jj = 0; jj < 4; jj++) {
            uint32_t row = wn * 64 + jj * 16 + lr;
            ldm_x4(bb[jj], bslab + sw128(row * 128u + kb));
        }
        #pragma unroll
        for (int i = 0; i < 4; i++) {
            #pragma unroll
            for (int j = 0; j < 8; j++) {
                uint32_t b0 = bb[j >> 1][j & 1];
                uint32_t b1 = bb[j >> 1][(j & 1) + 2];
                mma_bf16(acc[i][j], ah[i], b0, b1);
                mma_bf16(acc[i][j], al[i], b0, b1);
            }
        }
    }

    // ---- epilogue: scale by nscale[col], store float2 pairs ----
    #pragma unroll
    for (int i = 0; i < 4; i++) {
        #pragma unroll
        for (int j = 0; j < 8; j++) {
            int r0 = qtile + wm * 64 + i * 16 + (lane >> 2);
            int cl = wn * 64 + j * 8 + 2 * (lane & 3);
            int c = ktile + cl;
            float s0 = nscs[cl], s1 = nscs[cl + 1];
            float2 v0 = make_float2(acc[i][j][0] * s0, acc[i][j][1] * s1);
            float2 v1 = make_float2(acc[i][j][2] * s0, acc[i][j][3] * s1);
            *(float2*)(out + (size_t)r0 * NK + c) = v0;
            *(float2*)(out + (size_t)(r0 + 8) * NK + c) = v1;
        }
    }
}

// ================================================================================
extern "C" void kernel_launch(void* const* d_in, const int* in_sizes, int n_in,
                              void* d_out, int out_size)
{
    const float* query    = (const float*)d_in[0];
    const float* residual = (const float*)d_in[1];
    const float* S        = (const float*)d_in[2];
    float* out = (float*)d_out;

    cudaFuncSetAttribute(qjl_prep_kernel,
                         cudaFuncAttributeMaxDynamicSharedMemorySize, PREP_SMEM_BYTES);
    cudaFuncSetAttribute(qjl_mma_kernel,
                         cudaFuncAttributeMaxDynamicSharedMemorySize, MAIN_SMEM_BYTES);

    qjl_prep_kernel<<<(NK + NQ) / PREP_ROWS, PREP_THREADS, PREP_SMEM_BYTES>>>(
        query, residual, S);

    // 32 k-tiles x 32 q-tiles
    qjl_mma_kernel<<<dim3(NK / 256, NQ / 128), MT3, MAIN_SMEM_BYTES>>>(out);
}

// round 9
// speedup vs baseline: 1.2871x; 1.2871x over previous
#include <cuda_runtime.h>
#include <cuda_bf16.h>
#include <cuda_fp16.h>
#include <cstdint>

// Problem constants (fixed by the dataset)
#define DHEAD 128
#define MPROJ 128
#define NQ    4096
#define NK    8192
#define SCALE_CONST 0.009791516698f  // sqrt(pi/2)/128

// ---------------- device-global scratch (pre-swizzled SW128 slab layout) -------
// g_q:     fp16 q_proj. 128-row tiles of 32KB; two 16KB slabs (64 cols each);
//          slab offset = sw128(row*128 + col*2).
// g_signs: fp16 ±1, same tiling (64 tiles of 128 key-rows).
__device__ __half g_signs[NK * MPROJ];
__device__ float  g_nscale[NK];
__device__ __half g_q[NQ * MPROJ];

__device__ __forceinline__ uint32_t sw128(uint32_t x) { return x ^ ((x >> 3) & 0x70); }

// ================================================================================
// Prep: fp32 GEMM rows @ S^T. 32 rows/block. NUMERICS IDENTICAL to prior rounds
// (sign decisions are boundary-sensitive); only output encoding changed (fp16).
//   blocks [0,256): residual -> signs (fp16 ±1, swizzled) + nscale
//   blocks [256,384): query  -> q_proj (fp16, swizzled)
// ================================================================================
#define PREP_ROWS 32
#define PREP_THREADS 256
#define PADP 129
#define PREP_SMEM_BYTES ((PREP_ROWS * PADP + MPROJ * PADP) * 4)

__global__ __launch_bounds__(PREP_THREADS)
void qjl_prep_kernel(const float* __restrict__ query,
                     const float* __restrict__ residual,
                     const float* __restrict__ S)
{
    extern __shared__ float smf[];
    float* Ash = smf;                       // [32][129]
    float* Ssh = smf + PREP_ROWS * PADP;    // [128][129]

    const int tid = threadIdx.x;
    const bool is_res = (blockIdx.x < (NK / PREP_ROWS));
    const int rbase = is_res ? blockIdx.x * PREP_ROWS
                             : (blockIdx.x - NK / PREP_ROWS) * PREP_ROWS;
    const float* src = is_res ? residual : query;

    const float4* gA = (const float4*)(src + (size_t)rbase * DHEAD);
    #pragma unroll
    for (int idx = tid; idx < PREP_ROWS * 32; idx += PREP_THREADS) {
        int r = idx >> 5, c4 = idx & 31;
        float4 v = gA[idx];
        float* d = Ash + r * PADP + c4 * 4;
        d[0] = v.x; d[1] = v.y; d[2] = v.z; d[3] = v.w;
    }
    const float4* gS = (const float4*)S;
    #pragma unroll
    for (int idx = tid; idx < MPROJ * 32; idx += PREP_THREADS) {
        int r = idx >> 5, c4 = idx & 31;
        float4 v = gS[idx];
        float* d = Ssh + r * PADP + c4 * 4;
        d[0] = v.x; d[1] = v.y; d[2] = v.z; d[3] = v.w;
    }
    __syncthreads();

    if (is_res && tid < PREP_ROWS) {
        float s = 0.f;
        #pragma unroll 8
        for (int k = 0; k < DHEAD; k++) {
            float a = Ash[tid * PADP + k];
            s += a * a;
        }
        g_nscale[rbase + tid] = sqrtf(s) * SCALE_CONST;
    }

    const int rg = tid & 15;   // 2 rows per thread
    const int cg = tid >> 4;   // 8 cols per thread

    float acc[2][8];
    #pragma unroll
    for (int i = 0; i < 2; i++)
        #pragma unroll
        for (int j = 0; j < 8; j++) acc[i][j] = 0.f;

    #pragma unroll 4
    for (int k = 0; k < DHEAD; k++) {
        float a[2], b[8];
        #pragma unroll
        for (int i = 0; i < 2; i++) a[i] = Ash[(2 * rg + i) * PADP + k];
        #pragma unroll
        for (int j = 0; j < 8; j++) b[j] = Ssh[(8 * cg + j) * PADP + k];
        #pragma unroll
        for (int i = 0; i < 2; i++)
            #pragma unroll
            for (int j = 0; j < 8; j++)
                acc[i][j] = fmaf(a[i], b[j], acc[i][j]);
    }

    const int col8 = 8 * cg;              // col base (0..120)
    if (is_res) {
        #pragma unroll
        for (int i = 0; i < 2; i++) {
            union { __half h[8]; uint4 u; } pk;
            #pragma unroll
            for (int j = 0; j < 8; j++)
                pk.h[j] = __float2half(acc[i][j] >= 0.f ? 1.f : -1.f);
            int row = rbase + 2 * rg + i;
            uint32_t off = (uint32_t)(row >> 7) * 32768u
                         + (uint32_t)(col8 >> 6) * 16384u
                         + sw128((uint32_t)(row & 127) * 128u + (uint32_t)(col8 & 63) * 2u);
            *(uint4*)((char*)g_signs + off) = pk.u;
        }
    } else {
        #pragma unroll
        for (int i = 0; i < 2; i++) {
            union { __half h[8]; uint4 u; } ph;
            #pragma unroll
            for (int j = 0; j < 8; j++)
                ph.h[j] = __float2half(acc[i][j]);
            int row = rbase + 2 * rg + i;
            uint32_t off = (uint32_t)(row >> 7) * 32768u
                         + (uint32_t)(col8 >> 6) * 16384u
                         + sw128((uint32_t)(row & 127) * 128u + (uint32_t)(col8 & 63) * 2u);
            *(uint4*)((char*)g_q + off) = ph.u;
        }
    }
}

// ================================================================================
// Main GEMM via mma.sync fp16 (single pass). CTA: q-tile 128 fixed, iterates over
// G=4 k-tiles of 128. A resident, B double-buffered with cp.async.
// 8 warps, warp tile 64x32. Pre-swizzled SW128 smem, linear fills.
// ================================================================================
#define G 4
#define MT3 256
#define SA   0                     // 32 KB A (two 16KB slabs)
#define SB   32768                 // 2 x 32 KB B
#define SNSC 98304                 // 2 x 512 B nscale
#define MAIN_SMEM_BYTES (98304 + 1024)

__device__ __forceinline__ void ldm_x4(uint32_t* r, uint32_t addr) {
    asm volatile("ldmatrix.sync.aligned.m8n8.x4.shared.b16 {%0,%1,%2,%3}, [%4];"
                 : "=r"(r[0]), "=r"(r[1]), "=r"(r[2]), "=r"(r[3])
                 : "r"(addr));
}

__device__ __forceinline__ void mma_fp16(float* d, const uint32_t* a,
                                         uint32_t b0, uint32_t b1) {
    asm volatile(
        "mma.sync.aligned.m16n8k16.row.col.f32.f16.f16.f32 "
        "{%0,%1,%2,%3}, {%4,%5,%6,%7}, {%8,%9}, {%0,%1,%2,%3};"
        : "+f"(d[0]), "+f"(d[1]), "+f"(d[2]), "+f"(d[3])
        : "r"(a[0]), "r"(a[1]), "r"(a[2]), "r"(a[3]), "r"(b0), "r"(b1));
}

__device__ __forceinline__ void cpa16(uint32_t s, const void* g) {
    asm volatile("cp.async.cg.shared.global [%0], [%1], 16;" :: "r"(s), "l"(g));
}
__device__ __forceinline__ void cpa_commit() {
    asm volatile("cp.async.commit_group;");
}
__device__ __forceinline__ void cpa_wait0() {
    asm volatile("cp.async.wait_group 0;");
}

__global__ __launch_bounds__(MT3, 2)
void qjl_mma2_kernel(float* __restrict__ out)
{
    extern __shared__ char smem[];
    uint32_t sb;
    asm("{ .reg .u64 t; cvta.to.shared.u64 t, %1; cvt.u32.u64 %0, t; }"
        : "=r"(sb) : "l"(smem));

    const int tid = threadIdx.x;
    const int warp = tid >> 5, lane = tid & 31;
    const int qtile  = blockIdx.y * 128;
    const int ktile0 = blockIdx.x * (G * 128);

    // ---- A fill (once) + B0 + nsc0, all cp.async (global layout pre-swizzled) --
    {
        const char* gA = (const char*)g_q + (size_t)(qtile >> 7) * 32768;
        #pragma unroll
        for (int i = tid; i < 2048; i += MT3)
            cpa16(sb + SA + i * 16, gA + i * 16);
        const char* gB = (const char*)g_signs + (size_t)(ktile0 >> 7) * 32768;
        #pragma unroll
        for (int i = tid; i < 2048; i += MT3)
            cpa16(sb + SB + i * 16, gB + i * 16);
        if (tid < 32)
            cpa16(sb + SNSC + tid * 16, (const char*)(g_nscale + ktile0) + tid * 16);
        cpa_commit();
    }

    const int wm = warp >> 2;          // 0..1  (M half)
    const int wn = warp & 3;           // 0..3  (N quarter)
    const int lr = lane & 15;
    const uint32_t lcB = (uint32_t)(lane >> 4) * 16u;

    #pragma unroll
    for (int it = 0; it < G; it++) {
        const int kt = ktile0 + it * 128;
        const int buf = it & 1;

        cpa_wait0();
        __syncthreads();   // B[it] visible; all warps done with buf from it-1

        if (it + 1 < G) {  // prefetch B[it+1] into the other buffer
            const int nb = (it + 1) & 1;
            const char* gB = (const char*)g_signs + (size_t)((kt + 128) >> 7) * 32768;
            #pragma unroll
            for (int i = tid; i < 2048; i += MT3)
                cpa16(sb + SB + nb * 32768 + i * 16, gB + i * 16);
            if (tid < 32)
                cpa16(sb + SNSC + nb * 512 + tid * 16,
                      (const char*)(g_nscale + kt + 128) + tid * 16);
            cpa_commit();
        }

        const uint32_t bbase = sb + SB + buf * 32768;
        const float* nscs = (const float*)(smem + SNSC + buf * 512);

        float acc[4][4][4];
        #pragma unroll
        for (int i = 0; i < 4; i++)
            #pragma unroll
            for (int j = 0; j < 4; j++)
                #pragma unroll
                for (int t = 0; t < 4; t++) acc[i][j][t] = 0.f;

        #pragma unroll
        for (int ks = 0; ks < 8; ks++) {
            const uint32_t kb = (uint32_t)(ks & 3) * 32u + lcB;
            const uint32_t aslab = sb + SA + (ks >> 2) * 16384;
            const uint32_t bslab = bbase + (ks >> 2) * 16384;

            uint32_t af[4][4], bf[2][4];
            #pragma unroll
            for (int i = 0; i < 4; i++) {
                uint32_t row = wm * 64 + i * 16 + lr;
                ldm_x4(af[i], aslab + sw128(row * 128u + kb));
            }
            #pragma unroll
            for (int jj = 0; jj < 2; jj++) {
                uint32_t row = wn * 32 + jj * 16 + lr;
                ldm_x4(bf[jj], bslab + sw128(row * 128u + kb));
            }
            #pragma unroll
            for (int i = 0; i < 4; i++) {
                #pragma unroll
                for (int j = 0; j < 4; j++) {
                    uint32_t b0 = bf[j >> 1][j & 1];
                    uint32_t b1 = bf[j >> 1][(j & 1) + 2];
                    mma_fp16(acc[i][j], af[i], b0, b1);
                }
            }
        }

        // ---- epilogue: scale by nscale[col], store ----
        #pragma unroll
        for (int i = 0; i < 4; i++) {
            #pragma unroll
            for (int j = 0; j < 4; j++) {
                int r0 = qtile + wm * 64 + i * 16 + (lane >> 2);
                int cl = wn * 32 + j * 8 + 2 * (lane & 3);
                int c = kt + cl;
                float s0 = nscs[cl], s1 = nscs[cl + 1];
                float2 v0 = make_float2(acc[i][j][0] * s0, acc[i][j][1] * s1);
                float2 v1 = make_float2(acc[i][j][2] * s0, acc[i][j][3] * s1);
                *(float2*)(out + (size_t)r0 * NK + c) = v0;
                *(float2*)(out + (size_t)(r0 + 8) * NK + c) = v1;
            }
        }
    }
}

// ================================================================================
extern "C" void kernel_launch(void* const* d_in, const int* in_sizes, int n_in,
                              void* d_out, int out_size)
{
    const float* query    = (const float*)d_in[0];
    const float* residual = (const float*)d_in[1];
    const float* S        = (const float*)d_in[2];
    float* out = (float*)d_out;

    cudaFuncSetAttribute(qjl_prep_kernel,
                         cudaFuncAttributeMaxDynamicSharedMemorySize, PREP_SMEM_BYTES);
    cudaFuncSetAttribute(qjl_mma2_kernel,
                         cudaFuncAttributeMaxDynamicSharedMemorySize, MAIN_SMEM_BYTES);

    qjl_prep_kernel<<<(NK + NQ) / PREP_ROWS, PREP_THREADS, PREP_SMEM_BYTES>>>(
        query, residual, S);

    // 16 k-groups (4 tiles each) x 32 q-tiles
    qjl_mma2_kernel<<<dim3(NK / (G * 128), NQ / 128), MT3, MAIN_SMEM_BYTES>>>(out);
}